// round 3
// baseline (speedup 1.0000x reference)
#include <cuda_runtime.h>
#include <cuda_bf16.h>
#include <cstddef>

// ---------------------------------------------------------------------------
// TTLinear. Phase A (3 big parallel GEMMs): Z=X@t_k.T, Y=X@t_v.T, Q=X@t_q.T.
// Phase B: ONE persistent kernel running all 128 sequential SGD steps with
// software grid barriers (8 per step). Graph has ~8 nodes total.
// Barrier spins are BOUNDED so a residency/sync bug degrades to wrong output
// (visible as rel_err) instead of a container-killing hang.
// ---------------------------------------------------------------------------

constexpr int T_  = 128;
constexpr int NB  = 256;
constexpr int DD  = 1024;
constexpr int HH  = 1024;
constexpr int H4  = 256;
constexpr int NH  = NB * HH;    // 262144
constexpr int MN  = NB * H4;    // 65536
constexpr float LR = 1e-3f;
constexpr float C2 = 2.0f / (float)(NB * HH);

// ------------------------- device scratch ----------------------------------
__device__ float g_Z[(size_t)T_ * NH];
__device__ float g_Y[(size_t)T_ * NH];
__device__ float g_Q[(size_t)T_ * NH];
__device__ float g_W1[H4 * HH];
__device__ float g_b1[H4];
__device__ float g_W2[HH * H4];
__device__ float g_b2[HH];
__device__ float g_a[MN];
__device__ float g_h[MN];
__device__ float g_h2[MN];
__device__ float g_da[MN];
__device__ float g_dr[NB * HH];
__device__ float g_part[8 * MN];

// grid barrier state
__device__ unsigned g_cnt = 0;
__device__ unsigned g_gen = 0;

// ------------------------------ helpers ------------------------------------
__device__ __forceinline__ float gelu_f(float x) {
    return 0.5f * x * (1.0f + erff(x * 0.70710678118654752f));
}
__device__ __forceinline__ float gelu_grad(float x) {
    float cdf = 0.5f * (1.0f + erff(x * 0.70710678118654752f));
    float pdf = 0.3989422804014327f * expf(-0.5f * x * x);
    return cdf + x * pdf;
}

// Bounded grid barrier: ~1M polls (~65 ms) max, then gives up (degrades to
// wrong output instead of hanging the container).
__device__ __forceinline__ void grid_sync(unsigned nb) {
    __syncthreads();
    if (threadIdx.x == 0) {
        unsigned gen = *(volatile unsigned*)&g_gen;
        __threadfence();                       // release my block's writes
        if (atomicAdd(&g_cnt, 1) == nb - 1) {
            g_cnt = 0;
            __threadfence();
            atomicAdd(&g_gen, 1);              // release all waiters
        } else {
            for (int spin = 0; spin < 1000000; spin++) {
                if (*(volatile unsigned*)&g_gen != gen) break;
                __nanosleep(64);
            }
        }
        __threadfence();                       // acquire
    }
    __syncthreads();
}

// ---------------------------------------------------------------------------
// Phase A: C[M,N] = A[M,K] @ B[N,K]^T   (128x128x16 tiles, 8x8/thread, 256 thr)
// ---------------------------------------------------------------------------
__global__ __launch_bounds__(256) void gemm_nt_big(
    const float* __restrict__ A, const float* __restrict__ B,
    float* __restrict__ C, int M, int N, int K)
{
    __shared__ float As[16][128];
    __shared__ float Bs[16][128];
    const int m0 = blockIdx.x * 128;
    const int n0 = blockIdx.y * 128;
    const int tid = threadIdx.x;
    const int tx = tid % 16, ty = tid / 16;

    float acc[8][8];
#pragma unroll
    for (int i = 0; i < 8; i++)
#pragma unroll
        for (int j = 0; j < 8; j++) acc[i][j] = 0.f;

    for (int k0 = 0; k0 < K; k0 += 16) {
#pragma unroll
        for (int i = 0; i < 2; i++) {
            int f = tid + i * 256;
            int row = f >> 2, c4 = f & 3;
            float4 va = *(const float4*)(A + (size_t)(m0 + row) * K + k0 + c4 * 4);
            As[c4 * 4 + 0][row] = va.x; As[c4 * 4 + 1][row] = va.y;
            As[c4 * 4 + 2][row] = va.z; As[c4 * 4 + 3][row] = va.w;
            float4 vb = *(const float4*)(B + (size_t)(n0 + row) * K + k0 + c4 * 4);
            Bs[c4 * 4 + 0][row] = vb.x; Bs[c4 * 4 + 1][row] = vb.y;
            Bs[c4 * 4 + 2][row] = vb.z; Bs[c4 * 4 + 3][row] = vb.w;
        }
        __syncthreads();
#pragma unroll
        for (int k = 0; k < 16; k++) {
            float4 a0 = *(const float4*)&As[k][ty * 8];
            float4 a1 = *(const float4*)&As[k][ty * 8 + 4];
            float4 b0 = *(const float4*)&Bs[k][tx * 8];
            float4 b1 = *(const float4*)&Bs[k][tx * 8 + 4];
            float av[8] = {a0.x, a0.y, a0.z, a0.w, a1.x, a1.y, a1.z, a1.w};
            float bv[8] = {b0.x, b0.y, b0.z, b0.w, b1.x, b1.y, b1.z, b1.w};
#pragma unroll
            for (int i = 0; i < 8; i++)
#pragma unroll
                for (int j = 0; j < 8; j++) acc[i][j] += av[i] * bv[j];
        }
        __syncthreads();
    }
#pragma unroll
    for (int i = 0; i < 8; i++) {
        float* cp = C + (size_t)(m0 + ty * 8 + i) * N + n0 + tx * 8;
        *(float4*)(cp)     = make_float4(acc[i][0], acc[i][1], acc[i][2], acc[i][3]);
        *(float4*)(cp + 4) = make_float4(acc[i][4], acc[i][5], acc[i][6], acc[i][7]);
    }
}

// ---------------------------------------------------------------------------
// Persistent Phase B tile primitives: 64x64 tile, 512 threads, 2x4 microtile.
// ---------------------------------------------------------------------------
struct Acc24 { float v[2][4]; };

__device__ __forceinline__ void acc_zero(Acc24& a) {
#pragma unroll
    for (int i = 0; i < 2; i++)
#pragma unroll
        for (int j = 0; j < 4; j++) a.v[i][j] = 0.f;
}

// A[m,k] (lda) · B[n,k]^T (ldb), k in [kbeg, kend)
__device__ __forceinline__ void tile_nt(
    const float* __restrict__ A, const float* __restrict__ B,
    float (*sA)[68], float (*sB)[68],
    int lda, int ldb, int m0, int n0, int kbeg, int kend, Acc24& acc)
{
    const int tid = threadIdx.x;
    const int row = tid >> 3, c2 = (tid & 7) * 2;
    const int tx = tid & 15, ty = tid >> 4;
    for (int k0 = kbeg; k0 < kend; k0 += 16) {
        float2 va = *(const float2*)(A + (size_t)(m0 + row) * lda + k0 + c2);
        float2 vb = *(const float2*)(B + (size_t)(n0 + row) * ldb + k0 + c2);
        __syncthreads();
        sA[c2][row] = va.x; sA[c2 + 1][row] = va.y;
        sB[c2][row] = vb.x; sB[c2 + 1][row] = vb.y;
        __syncthreads();
#pragma unroll
        for (int k = 0; k < 16; k++) {
            float a0 = sA[k][ty * 2], a1 = sA[k][ty * 2 + 1];
            float4 b = *(const float4*)&sB[k][tx * 4];
#pragma unroll
            for (int j = 0; j < 4; j++) {
                float bj = (&b.x)[j];
                acc.v[0][j] += a0 * bj;
                acc.v[1][j] += a1 * bj;
            }
        }
    }
    __syncthreads();
}

// A[m,k] (lda) · B[k,n] (ldb), k in [kbeg, kend)
__device__ __forceinline__ void tile_nn(
    const float* __restrict__ A, const float* __restrict__ B,
    float (*sA)[68], float (*sB)[68],
    int lda, int ldb, int m0, int n0, int kbeg, int kend, Acc24& acc)
{
    const int tid = threadIdx.x;
    const int row = tid >> 3, c2 = (tid & 7) * 2;
    const int kr = tid >> 5, nc = (tid & 31) * 2;
    const int tx = tid & 15, ty = tid >> 4;
    for (int k0 = kbeg; k0 < kend; k0 += 16) {
        float2 va = *(const float2*)(A + (size_t)(m0 + row) * lda + k0 + c2);
        float2 vb = *(const float2*)(B + (size_t)(k0 + kr) * ldb + n0 + nc);
        __syncthreads();
        sA[c2][row] = va.x; sA[c2 + 1][row] = va.y;
        sB[kr][nc] = vb.x; sB[kr][nc + 1] = vb.y;
        __syncthreads();
#pragma unroll
        for (int k = 0; k < 16; k++) {
            float a0 = sA[k][ty * 2], a1 = sA[k][ty * 2 + 1];
            float4 b = *(const float4*)&sB[k][tx * 4];
#pragma unroll
            for (int j = 0; j < 4; j++) {
                float bj = (&b.x)[j];
                acc.v[0][j] += a0 * bj;
                acc.v[1][j] += a1 * bj;
            }
        }
    }
    __syncthreads();
}

// out[j,i] over A[k,j] (lda), B[k,i] (ldb), k in [0, Kn)
__device__ __forceinline__ void tile_tn(
    const float* __restrict__ A, const float* __restrict__ B,
    float (*sA)[68], float (*sB)[68],
    int lda, int ldb, int j0, int i0, int Kn, Acc24& acc)
{
    const int tid = threadIdx.x;
    const int kr = tid >> 5, c2 = (tid & 31) * 2;
    const int tx = tid & 15, ty = tid >> 4;
    for (int k0 = 0; k0 < Kn; k0 += 16) {
        float2 va = *(const float2*)(A + (size_t)(k0 + kr) * lda + j0 + c2);
        float2 vb = *(const float2*)(B + (size_t)(k0 + kr) * ldb + i0 + c2);
        __syncthreads();
        sA[kr][c2] = va.x; sA[kr][c2 + 1] = va.y;
        sB[kr][c2] = vb.x; sB[kr][c2 + 1] = vb.y;
        __syncthreads();
#pragma unroll
        for (int k = 0; k < 16; k++) {
            float a0 = sA[k][ty * 2], a1 = sA[k][ty * 2 + 1];
            float4 b = *(const float4*)&sB[k][tx * 4];
#pragma unroll
            for (int j = 0; j < 4; j++) {
                float bj = (&b.x)[j];
                acc.v[0][j] += a0 * bj;
                acc.v[1][j] += a1 * bj;
            }
        }
    }
    __syncthreads();
}

// ---------------------------------------------------------------------------
// Persistent Phase B kernel
// ---------------------------------------------------------------------------
__global__ __launch_bounds__(512, 1) void ttt_persistent(float* __restrict__ out,
                                                         int nb)
{
    __shared__ float sA[16][68];
    __shared__ float sB[16][68];
    const int bid = blockIdx.x;
    const int tid = threadIdx.x;
    const int tx = tid & 15, ty = tid >> 4;

    for (int step = 0; step <= T_; step++) {
        // R0: S10 of step-1 (64 units) + S1 split-K partials of step (128 units)
        int n9 = (step > 0) ? 64 : 0;
        for (int u = bid; u < n9 + ((step < T_) ? 128 : 0); u += nb) {
            if (u < n9) {
                int t = step - 1;
                const float* Qt = g_Q + (size_t)t * NH;
                int m0 = (u & 3) * 64, n0 = (u >> 2) * 64;
                Acc24 acc; acc_zero(acc);
                tile_nt(g_h2, g_W2, sA, sB, H4, H4, m0, n0, 0, H4, acc);
                const int n = n0 + tx * 4;
                float4 bb = *(const float4*)(g_b2 + n);
                float* od = out + (size_t)t * NH;
#pragma unroll
                for (int r = 0; r < 2; r++) {
                    int m = m0 + ty * 2 + r;
                    float4 q = *(const float4*)(Qt + (size_t)m * HH + n);
                    *(float4*)(od + (size_t)m * HH + n) = make_float4(
                        q.x + acc.v[r][0] + bb.x, q.y + acc.v[r][1] + bb.y,
                        q.z + acc.v[r][2] + bb.z, q.w + acc.v[r][3] + bb.w);
                }
            } else {
                int v = u - n9;
                const float* Zt = g_Z + (size_t)step * NH;
                int sk = v & 7, tile = v >> 3;
                int m0 = (tile & 3) * 64, n0 = (tile >> 2) * 64;
                Acc24 acc; acc_zero(acc);
                tile_nt(Zt, g_W1, sA, sB, DD, DD, m0, n0, sk * 128, sk * 128 + 128, acc);
                float* cp = g_part + (size_t)sk * MN;
#pragma unroll
                for (int r = 0; r < 2; r++)
                    *(float4*)(cp + (size_t)(m0 + ty * 2 + r) * H4 + n0 + tx * 4) =
                        make_float4(acc.v[r][0], acc.v[r][1], acc.v[r][2], acc.v[r][3]);
            }
        }
        grid_sync(nb);
        if (step == T_) break;

        const int t = step;
        const float* Zt = g_Z + (size_t)t * NH;
        const float* Yt = g_Y + (size_t)t * NH;
        const float* Qt = g_Q + (size_t)t * NH;

        // R1: a = sum(part)+b1, h = gelu(a)
        for (int idx = bid * 512 + tid; idx < MN; idx += nb * 512) {
            float s = 0.f;
#pragma unroll
            for (int z = 0; z < 8; z++) s += g_part[(size_t)z * MN + idx];
            s += g_b1[idx & (H4 - 1)];
            g_a[idx] = s;
            g_h[idx] = gelu_f(s);
        }
        grid_sync(nb);

        // R2: dr = C2*(Zt + h@W2^T + b2 - Yt)   (64 tiles), OLD W2
        for (int u = bid; u < 64; u += nb) {
            int m0 = (u & 3) * 64, n0 = (u >> 2) * 64;
            Acc24 acc; acc_zero(acc);
            tile_nt(g_h, g_W2, sA, sB, H4, H4, m0, n0, 0, H4, acc);
            const int n = n0 + tx * 4;
            float4 bb = *(const float4*)(g_b2 + n);
#pragma unroll
            for (int r = 0; r < 2; r++) {
                int m = m0 + ty * 2 + r;
                float4 zz = *(const float4*)(Zt + (size_t)m * HH + n);
                float4 yy = *(const float4*)(Yt + (size_t)m * HH + n);
                *(float4*)(g_dr + (size_t)m * HH + n) = make_float4(
                    C2 * (zz.x + acc.v[r][0] + bb.x - yy.x),
                    C2 * (zz.y + acc.v[r][1] + bb.y - yy.y),
                    C2 * (zz.z + acc.v[r][2] + bb.z - yy.z),
                    C2 * (zz.w + acc.v[r][3] + bb.w - yy.w));
            }
        }
        grid_sync(nb);

        // R3: da_pre partials = dr @ W2 (NN, split-K), OLD W2
        for (int u = bid; u < 128; u += nb) {
            int sk = u & 7, tile = u >> 3;
            int m0 = (tile & 3) * 64, n0 = (tile >> 2) * 64;
            Acc24 acc; acc_zero(acc);
            tile_nn(g_dr, g_W2, sA, sB, HH, H4, m0, n0, sk * 128, sk * 128 + 128, acc);
            float* cp = g_part + (size_t)sk * MN;
#pragma unroll
            for (int r = 0; r < 2; r++)
                *(float4*)(cp + (size_t)(m0 + ty * 2 + r) * H4 + n0 + tx * 4) =
                    make_float4(acc.v[r][0], acc.v[r][1], acc.v[r][2], acc.v[r][3]);
        }
        grid_sync(nb);

        // R4: da = sum(part) * gelu'(a)
        for (int idx = bid * 512 + tid; idx < MN; idx += nb * 512) {
            float s = 0.f;
#pragma unroll
            for (int z = 0; z < 8; z++) s += g_part[(size_t)z * MN + idx];
            g_da[idx] = s * gelu_grad(g_a[idx]);
        }
        grid_sync(nb);

        // R5: parameter updates (131 units)
        for (int u = bid; u < 131; u += nb) {
            if (u < 64) {
                int i0 = (u & 15) * 64, j0 = (u >> 4) * 64;
                Acc24 acc; acc_zero(acc);
                tile_tn(g_dr, g_h, sA, sB, HH, H4, i0, j0, NB, acc);
#pragma unroll
                for (int r = 0; r < 2; r++) {
                    float* pp = g_W2 + (size_t)(i0 + ty * 2 + r) * H4 + j0 + tx * 4;
                    float4 o = *(float4*)pp;
                    o.x -= LR * acc.v[r][0]; o.y -= LR * acc.v[r][1];
                    o.z -= LR * acc.v[r][2]; o.w -= LR * acc.v[r][3];
                    *(float4*)pp = o;
                }
            } else if (u < 128) {
                int v = u - 64;
                int j0 = (v & 3) * 64, i0 = (v >> 2) * 64;
                Acc24 acc; acc_zero(acc);
                tile_tn(g_da, Zt, sA, sB, H4, DD, j0, i0, NB, acc);
#pragma unroll
                for (int r = 0; r < 2; r++) {
                    float* pp = g_W1 + (size_t)(j0 + ty * 2 + r) * DD + i0 + tx * 4;
                    float4 o = *(float4*)pp;
                    o.x -= LR * acc.v[r][0]; o.y -= LR * acc.v[r][1];
                    o.z -= LR * acc.v[r][2]; o.w -= LR * acc.v[r][3];
                    *(float4*)pp = o;
                }
            } else if (u < 130) {
                int c = (u - 128) * 512 + tid;
                float s = 0.f;
                for (int n = 0; n < NB; n++) s += g_dr[(size_t)n * HH + c];
                g_b2[c] -= LR * s;
            } else {
                if (tid < H4) {
                    float s = 0.f;
                    for (int n = 0; n < NB; n++) s += g_da[(size_t)n * H4 + tid];
                    g_b1[tid] -= LR * s;
                }
            }
        }
        grid_sync(nb);

        // R6: a2 partials = Qt @ W1_new^T (split-K)
        for (int u = bid; u < 128; u += nb) {
            int sk = u & 7, tile = u >> 3;
            int m0 = (tile & 3) * 64, n0 = (tile >> 2) * 64;
            Acc24 acc; acc_zero(acc);
            tile_nt(Qt, g_W1, sA, sB, DD, DD, m0, n0, sk * 128, sk * 128 + 128, acc);
            float* cp = g_part + (size_t)sk * MN;
#pragma unroll
            for (int r = 0; r < 2; r++)
                *(float4*)(cp + (size_t)(m0 + ty * 2 + r) * H4 + n0 + tx * 4) =
                    make_float4(acc.v[r][0], acc.v[r][1], acc.v[r][2], acc.v[r][3]);
        }
        grid_sync(nb);

        // R7: h2 = gelu(sum(part) + b1_new)
        for (int idx = bid * 512 + tid; idx < MN; idx += nb * 512) {
            float s = 0.f;
#pragma unroll
            for (int z = 0; z < 8; z++) s += g_part[(size_t)z * MN + idx];
            s += g_b1[idx & (H4 - 1)];
            g_h2[idx] = gelu_f(s);
        }
        grid_sync(nb);
        // loop back: R0 emits this step's output (+ next step's S1)
    }
}

// ---------------------------------------------------------------------------
// kernel_launch
// ---------------------------------------------------------------------------
extern "C" void kernel_launch(void* const* d_in, const int* in_sizes, int n_in,
                              void* d_out, int out_size)
{
    (void)in_sizes; (void)n_in; (void)out_size;
    const float* in_seq = (const float*)d_in[0];
    const float* t_k = (const float*)d_in[1];
    const float* t_v = (const float*)d_in[2];
    const float* t_q = (const float*)d_in[3];

    float *Z, *Y, *Q, *W1, *b1, *W2, *b2;
    cudaGetSymbolAddress((void**)&Z, g_Z);
    cudaGetSymbolAddress((void**)&Y, g_Y);
    cudaGetSymbolAddress((void**)&Q, g_Q);
    cudaGetSymbolAddress((void**)&W1, g_W1);
    cudaGetSymbolAddress((void**)&b1, g_b1);
    cudaGetSymbolAddress((void**)&W2, g_W2);
    cudaGetSymbolAddress((void**)&b2, g_b2);

    cudaMemcpyAsync(W1, d_in[4], sizeof(float) * H4 * HH, cudaMemcpyDeviceToDevice, 0);
    cudaMemcpyAsync(b1, d_in[5], sizeof(float) * H4, cudaMemcpyDeviceToDevice, 0);
    cudaMemcpyAsync(W2, d_in[6], sizeof(float) * HH * H4, cudaMemcpyDeviceToDevice, 0);
    cudaMemcpyAsync(b2, d_in[7], sizeof(float) * HH, cudaMemcpyDeviceToDevice, 0);

    // Phase A
    const int M_big = T_ * NB;
    dim3 gA(M_big / 128, HH / 128);
    gemm_nt_big<<<gA, 256>>>(in_seq, t_k, Z, M_big, HH, DD);
    gemm_nt_big<<<gA, 256>>>(in_seq, t_v, Y, M_big, HH, DD);
    gemm_nt_big<<<gA, 256>>>(in_seq, t_q, Q, M_big, HH, DD);

    // Phase B: one persistent kernel, exactly one block per SM.
    int sms = 0;
    cudaDeviceGetAttribute(&sms, cudaDevAttrMultiProcessorCount, 0);
    if (sms <= 0 || sms > 148) sms = 148;
    ttt_persistent<<<sms, 512>>>((float*)d_out, sms);
}

// round 4
// speedup vs baseline: 1.0022x; 1.0022x over previous
#include <cuda_runtime.h>
#include <cuda_bf16.h>
#include <cstdint>
#include <cstddef>

// ---------------------------------------------------------------------------
// TTLinear. Phase A: 3 big GEMMs (tf32 tensor cores). Phase B: one persistent
// kernel, 128 sequential SGD steps, 8 grid barriers/step, double-buffered
// fp32 tiles with half-block pairing (two 64x64 units per 512-thread block).
// ---------------------------------------------------------------------------

constexpr int T_  = 128;
constexpr int NB  = 256;
constexpr int DD  = 1024;
constexpr int HH  = 1024;
constexpr int H4  = 256;
constexpr int NH  = NB * HH;    // 262144
constexpr int MN  = NB * H4;    // 65536
constexpr float LR = 1e-3f;
constexpr float C2 = 2.0f / (float)(NB * HH);

constexpr int SL   = 68;        // padded smem row (floats)
constexpr int SLAB = 16 * SL;   // one k-slab buffer

// ------------------------- device scratch ----------------------------------
__device__ float g_Z[(size_t)T_ * NH];
__device__ float g_Y[(size_t)T_ * NH];
__device__ float g_Q[(size_t)T_ * NH];
__device__ float g_W1[H4 * HH];
__device__ float g_b1[H4];
__device__ float g_W2[HH * H4];
__device__ float g_b2[HH];
__device__ float g_a[MN];
__device__ float g_h[MN];
__device__ float g_h2[MN];
__device__ float g_da[MN];
__device__ float g_dr[NB * HH];
__device__ float g_part[8 * MN];

__device__ unsigned g_cnt = 0;
__device__ unsigned g_gen = 0;

// ------------------------------ helpers ------------------------------------
__device__ __forceinline__ float gelu_f(float x) {
    return 0.5f * x * (1.0f + erff(x * 0.70710678118654752f));
}
__device__ __forceinline__ float gelu_grad(float x) {
    float cdf = 0.5f * (1.0f + erff(x * 0.70710678118654752f));
    float pdf = 0.3989422804014327f * expf(-0.5f * x * x);
    return cdf + x * pdf;
}
__device__ __forceinline__ float to_tf32(float x) {
    uint32_t u;
    asm("cvt.rna.tf32.f32 %0, %1;" : "=r"(u) : "f"(x));
    return __uint_as_float(u);
}
__device__ __forceinline__ void mma_tf32(float (&c)[4], const uint32_t (&a)[4],
                                         const uint32_t (&b)[2]) {
    asm volatile(
        "mma.sync.aligned.m16n8k8.row.col.f32.tf32.tf32.f32 "
        "{%0,%1,%2,%3}, {%4,%5,%6,%7}, {%8,%9}, {%0,%1,%2,%3};"
        : "+f"(c[0]), "+f"(c[1]), "+f"(c[2]), "+f"(c[3])
        : "r"(a[0]), "r"(a[1]), "r"(a[2]), "r"(a[3]), "r"(b[0]), "r"(b[1]));
}

// Bounded grid barrier (degrades to wrong output, never hangs the container).
__device__ __forceinline__ void grid_sync(unsigned nb) {
    __syncthreads();
    if (threadIdx.x == 0) {
        unsigned gen = *(volatile unsigned*)&g_gen;
        __threadfence();
        if (atomicAdd(&g_cnt, 1) == nb - 1) {
            g_cnt = 0;
            __threadfence();
            atomicAdd(&g_gen, 1);
        } else {
            for (int spin = 0; spin < 1000000; spin++) {
                if (*(volatile unsigned*)&g_gen != gen) break;
                __nanosleep(32);
            }
        }
        __threadfence();
    }
    __syncthreads();
}

// ---------------------------------------------------------------------------
// Phase A: C[M,N] = A[M,K] @ B[N,K]^T via tf32 mma.sync. 128x128 block tile,
// 256 threads = 8 warps (2x4), warp tile 64x32, double-buffered smem.
// ---------------------------------------------------------------------------
__global__ __launch_bounds__(256, 2) void gemm_nt_tf32(
    const float* __restrict__ A, const float* __restrict__ B,
    float* __restrict__ C, int M, int N, int K)
{
    __shared__ float As[2][16][136];
    __shared__ float Bs[2][16][136];
    const int m0 = blockIdx.x * 128, n0 = blockIdx.y * 128;
    const int tid = threadIdx.x;
    const int lrow = tid & 127, lc8 = (tid >> 7) * 8;
    const int w = tid >> 5, lane = tid & 31;
    const int wm = w >> 2, wn = w & 3;
    const int g = lane >> 2, q = lane & 3;

    float acc[4][4][4] = {};

    const float* Ag = A + (size_t)(m0 + lrow) * K + lc8;
    const float* Bg = B + (size_t)(n0 + lrow) * K + lc8;

    float4 ra0 = *(const float4*)(Ag);
    float4 ra1 = *(const float4*)(Ag + 4);
    float4 rb0 = *(const float4*)(Bg);
    float4 rb1 = *(const float4*)(Bg + 4);

    const int S = K / 16;
    for (int s = 0; s < S; s++) {
        const int buf = s & 1;
        {   // store current regs -> smem (tf32-rounded)
            float* pa = &As[buf][lc8][lrow];
            pa[0*136] = to_tf32(ra0.x); pa[1*136] = to_tf32(ra0.y);
            pa[2*136] = to_tf32(ra0.z); pa[3*136] = to_tf32(ra0.w);
            pa[4*136] = to_tf32(ra1.x); pa[5*136] = to_tf32(ra1.y);
            pa[6*136] = to_tf32(ra1.z); pa[7*136] = to_tf32(ra1.w);
            float* pb = &Bs[buf][lc8][lrow];
            pb[0*136] = to_tf32(rb0.x); pb[1*136] = to_tf32(rb0.y);
            pb[2*136] = to_tf32(rb0.z); pb[3*136] = to_tf32(rb0.w);
            pb[4*136] = to_tf32(rb1.x); pb[5*136] = to_tf32(rb1.y);
            pb[6*136] = to_tf32(rb1.z); pb[7*136] = to_tf32(rb1.w);
        }
        if (s + 1 < S) {   // prefetch next slab
            const float* a2 = Ag + (s + 1) * 16;
            const float* b2 = Bg + (s + 1) * 16;
            ra0 = *(const float4*)(a2);     ra1 = *(const float4*)(a2 + 4);
            rb0 = *(const float4*)(b2);     rb1 = *(const float4*)(b2 + 4);
        }
        __syncthreads();
#pragma unroll
        for (int kc = 0; kc < 16; kc += 8) {
            uint32_t af[4][4], bf[4][2];
#pragma unroll
            for (int mt = 0; mt < 4; mt++) {
                int r = wm * 64 + mt * 16 + g;
                af[mt][0] = __float_as_uint(As[buf][kc + q][r]);
                af[mt][1] = __float_as_uint(As[buf][kc + q][r + 8]);
                af[mt][2] = __float_as_uint(As[buf][kc + q + 4][r]);
                af[mt][3] = __float_as_uint(As[buf][kc + q + 4][r + 8]);
            }
#pragma unroll
            for (int nt = 0; nt < 4; nt++) {
                int c = wn * 32 + nt * 8 + g;
                bf[nt][0] = __float_as_uint(Bs[buf][kc + q][c]);
                bf[nt][1] = __float_as_uint(Bs[buf][kc + q + 4][c]);
            }
#pragma unroll
            for (int mt = 0; mt < 4; mt++)
#pragma unroll
                for (int nt = 0; nt < 4; nt++)
                    mma_tf32(acc[mt][nt], af[mt], bf[nt]);
        }
        __syncthreads();
    }
#pragma unroll
    for (int mt = 0; mt < 4; mt++)
#pragma unroll
        for (int nt = 0; nt < 4; nt++) {
            int r = m0 + wm * 64 + mt * 16 + g;
            int c = n0 + wn * 32 + nt * 8 + q * 2;
            *(float2*)&C[(size_t)r * N + c] =
                make_float2(acc[mt][nt][0], acc[mt][nt][1]);
            *(float2*)&C[(size_t)(r + 8) * N + c] =
                make_float2(acc[mt][nt][2], acc[mt][nt][3]);
        }
}

// ---------------------------------------------------------------------------
// Phase B tile primitive: 64x64 tile, 256 threads (one half-block), 4x4
// microtile, double-buffered smem, ONE __syncthreads per 16-k slab.
// MODE 0 NT: A[m,k],B[n,k]; MODE 1 NN: A[m,k],B[k,n]; MODE 2 TN: A[k,m],B[k,n]
// ---------------------------------------------------------------------------
template <int MODE>
__device__ __forceinline__ void tile_db(
    const float* __restrict__ A, const float* __restrict__ B, float* hsm,
    int lda, int ldb, int m0, int n0, int kbeg, int kend, int htid,
    float (&acc)[4][4])
{
    float* smA = hsm;
    float* smB = hsm + 2 * SLAB;
    const int rowm = htid >> 2,  c4m = (htid & 3) * 4;
    const int krow = htid >> 4,  c4k = (htid & 15) * 4;
    const int tx = htid & 15,    ty = htid >> 4;
    const int nslab = (kend - kbeg) >> 4;
    float4 ra, rb;

    {   // fetch slab 0
        int k0 = kbeg;
        ra = (MODE == 2) ? *(const float4*)(A + (size_t)(k0 + krow) * lda + m0 + c4k)
                         : *(const float4*)(A + (size_t)(m0 + rowm) * lda + k0 + c4m);
        rb = (MODE == 0) ? *(const float4*)(B + (size_t)(n0 + rowm) * ldb + k0 + c4m)
                         : *(const float4*)(B + (size_t)(k0 + krow) * ldb + n0 + c4k);
    }
    for (int s = 0; s < nslab; s++) {
        const int buf = s & 1;
        {   // store current regs
            float* dA = smA + buf * SLAB;
            float* dB = smB + buf * SLAB;
            if (MODE == 2) { *(float4*)(dA + krow * SL + c4k) = ra; }
            else {
                dA[(c4m + 0) * SL + rowm] = ra.x; dA[(c4m + 1) * SL + rowm] = ra.y;
                dA[(c4m + 2) * SL + rowm] = ra.z; dA[(c4m + 3) * SL + rowm] = ra.w;
            }
            if (MODE == 0) {
                dB[(c4m + 0) * SL + rowm] = rb.x; dB[(c4m + 1) * SL + rowm] = rb.y;
                dB[(c4m + 2) * SL + rowm] = rb.z; dB[(c4m + 3) * SL + rowm] = rb.w;
            } else { *(float4*)(dB + krow * SL + c4k) = rb; }
        }
        if (s + 1 < nslab) {   // prefetch next slab
            int k0 = kbeg + (s + 1) * 16;
            ra = (MODE == 2) ? *(const float4*)(A + (size_t)(k0 + krow) * lda + m0 + c4k)
                             : *(const float4*)(A + (size_t)(m0 + rowm) * lda + k0 + c4m);
            rb = (MODE == 0) ? *(const float4*)(B + (size_t)(n0 + rowm) * ldb + k0 + c4m)
                             : *(const float4*)(B + (size_t)(k0 + krow) * ldb + n0 + c4k);
        }
        __syncthreads();
        const float* cA = smA + buf * SLAB;
        const float* cB = smB + buf * SLAB;
#pragma unroll
        for (int k = 0; k < 16; k++) {
            float4 a = *(const float4*)(cA + k * SL + ty * 4);
            float4 b = *(const float4*)(cB + k * SL + tx * 4);
            float av[4] = {a.x, a.y, a.z, a.w};
            float bv[4] = {b.x, b.y, b.z, b.w};
#pragma unroll
            for (int i = 0; i < 4; i++)
#pragma unroll
                for (int j = 0; j < 4; j++) acc[i][j] += av[i] * bv[j];
        }
        __syncthreads();
    }
}

// ---------------------------------------------------------------------------
// Persistent Phase B kernel: 512 threads, two 64x64 tile-units per block
// (halves run in lockstep; all per-region unit counts are even).
// ---------------------------------------------------------------------------
__global__ __launch_bounds__(512, 1) void ttt_persistent(float* __restrict__ out,
                                                         int nb)
{
    __shared__ __align__(16) float PB[2][4 * SLAB];
    const int bid = blockIdx.x, tid = threadIdx.x;
    const int half = tid >> 8, htid = tid & 255;
    const int tx = htid & 15, ty = htid >> 4;
    float* hsm = PB[half];
    const int ustride = nb * 2;
    const int ubase = bid * 2 + half;
    const int gw = (bid * 512 + tid) >> 5, lane = tid & 31;

    for (int step = 0; step <= T_; step++) {
        // ---- R0a: S10 of step-1: out[t-1] = Qt + h2@W2^T + b2 (64 units) ----
        if (step > 0) {
            const int t = step - 1;
            const float* Qt = g_Q + (size_t)t * NH;
            float* od = out + (size_t)t * NH;
            for (int u = ubase; u < 64; u += ustride) {
                int m0 = (u & 3) * 64, n0 = (u >> 2) * 64;
                float acc[4][4] = {};
                tile_db<0>(g_h2, g_W2, hsm, H4, H4, m0, n0, 0, H4, htid, acc);
                int n = n0 + tx * 4;
                float4 bb = *(const float4*)(g_b2 + n);
#pragma unroll
                for (int r = 0; r < 4; r++) {
                    int m = m0 + ty * 4 + r;
                    float4 qv = *(const float4*)(Qt + (size_t)m * HH + n);
                    *(float4*)(od + (size_t)m * HH + n) = make_float4(
                        qv.x + acc[r][0] + bb.x, qv.y + acc[r][1] + bb.y,
                        qv.z + acc[r][2] + bb.z, qv.w + acc[r][3] + bb.w);
                }
            }
        }
        // ---- R0b: S1 split-K partials: Zt @ W1^T (128 units) ----
        if (step < T_) {
            const float* Zt = g_Z + (size_t)step * NH;
            for (int u = ubase; u < 128; u += ustride) {
                int sk = u & 7, tile = u >> 3;
                int m0 = (tile & 3) * 64, n0 = (tile >> 2) * 64;
                float acc[4][4] = {};
                tile_db<0>(Zt, g_W1, hsm, DD, DD, m0, n0, sk * 128, sk * 128 + 128,
                           htid, acc);
                float* cp = g_part + (size_t)sk * MN;
#pragma unroll
                for (int r = 0; r < 4; r++)
                    *(float4*)(cp + (size_t)(m0 + ty * 4 + r) * H4 + n0 + tx * 4) =
                        make_float4(acc[r][0], acc[r][1], acc[r][2], acc[r][3]);
            }
        }
        grid_sync(nb);
        if (step == T_) break;

        const int t = step;
        const float* Zt = g_Z + (size_t)t * NH;
        const float* Yt = g_Y + (size_t)t * NH;
        const float* Qt = g_Q + (size_t)t * NH;

        // ---- R1: a = sum(part)+b1; h = gelu(a) ----
        for (int idx = bid * 512 + tid; idx < MN; idx += nb * 512) {
            float s = 0.f;
#pragma unroll
            for (int z = 0; z < 8; z++) s += g_part[(size_t)z * MN + idx];
            s += g_b1[idx & (H4 - 1)];
            g_a[idx] = s;
            g_h[idx] = gelu_f(s);
        }
        grid_sync(nb);

        // ---- R2: dr = C2*(Zt + h@W2^T + b2 - Yt) (64 units, OLD W2) ----
        for (int u = ubase; u < 64; u += ustride) {
            int m0 = (u & 3) * 64, n0 = (u >> 2) * 64;
            float acc[4][4] = {};
            tile_db<0>(g_h, g_W2, hsm, H4, H4, m0, n0, 0, H4, htid, acc);
            int n = n0 + tx * 4;
            float4 bb = *(const float4*)(g_b2 + n);
#pragma unroll
            for (int r = 0; r < 4; r++) {
                int m = m0 + ty * 4 + r;
                float4 zz = *(const float4*)(Zt + (size_t)m * HH + n);
                float4 yy = *(const float4*)(Yt + (size_t)m * HH + n);
                *(float4*)(g_dr + (size_t)m * HH + n) = make_float4(
                    C2 * (zz.x + acc[r][0] + bb.x - yy.x),
                    C2 * (zz.y + acc[r][1] + bb.y - yy.y),
                    C2 * (zz.z + acc[r][2] + bb.z - yy.z),
                    C2 * (zz.w + acc[r][3] + bb.w - yy.w));
            }
        }
        grid_sync(nb);

        // ---- R3: da_pre partials = dr @ W2 (NN, 128 units, OLD W2) ----
        for (int u = ubase; u < 128; u += ustride) {
            int sk = u & 7, tile = u >> 3;
            int m0 = (tile & 3) * 64, n0 = (tile >> 2) * 64;
            float acc[4][4] = {};
            tile_db<1>(g_dr, g_W2, hsm, HH, H4, m0, n0, sk * 128, sk * 128 + 128,
                       htid, acc);
            float* cp = g_part + (size_t)sk * MN;
#pragma unroll
            for (int r = 0; r < 4; r++)
                *(float4*)(cp + (size_t)(m0 + ty * 4 + r) * H4 + n0 + tx * 4) =
                    make_float4(acc[r][0], acc[r][1], acc[r][2], acc[r][3]);
        }
        grid_sync(nb);

        // ---- R4: da = sum(part) * gelu'(a) ----
        for (int idx = bid * 512 + tid; idx < MN; idx += nb * 512) {
            float s = 0.f;
#pragma unroll
            for (int z = 0; z < 8; z++) s += g_part[(size_t)z * MN + idx];
            g_da[idx] = s * gelu_grad(g_a[idx]);
        }
        grid_sync(nb);

        // ---- R5: W2/W1 updates (128 TN units, Kn=256) + bias colsums ----
        for (int u = ubase; u < 128; u += ustride) {
            if (u < 64) {
                int i0 = (u & 15) * 64, j0 = (u >> 4) * 64;
                float acc[4][4] = {};
                tile_db<2>(g_dr, g_h, hsm, HH, H4, i0, j0, 0, NB, htid, acc);
#pragma unroll
                for (int r = 0; r < 4; r++) {
                    float* pp = g_W2 + (size_t)(i0 + ty * 4 + r) * H4 + j0 + tx * 4;
                    float4 o = *(float4*)pp;
                    o.x -= LR * acc[r][0]; o.y -= LR * acc[r][1];
                    o.z -= LR * acc[r][2]; o.w -= LR * acc[r][3];
                    *(float4*)pp = o;
                }
            } else {
                int v = u - 64;
                int j0 = (v & 3) * 64, i0 = (v >> 2) * 64;
                float acc[4][4] = {};
                tile_db<2>(g_da, Zt, hsm, H4, DD, j0, i0, 0, NB, htid, acc);
#pragma unroll
                for (int r = 0; r < 4; r++) {
                    float* pp = g_W1 + (size_t)(j0 + ty * 4 + r) * DD + i0 + tx * 4;
                    float4 o = *(float4*)pp;
                    o.x -= LR * acc[r][0]; o.y -= LR * acc[r][1];
                    o.z -= LR * acc[r][2]; o.w -= LR * acc[r][3];
                    *(float4*)pp = o;
                }
            }
        }
        // bias updates: warp-parallel column sums (no syncs -> safe divergence)
        for (int c = gw; c < HH; c += nb * 16) {
            float s = 0.f;
            for (int n = lane; n < NB; n += 32) s += g_dr[(size_t)n * HH + c];
#pragma unroll
            for (int o = 16; o > 0; o >>= 1) s += __shfl_xor_sync(0xffffffffu, s, o);
            if (lane == 0) g_b2[c] -= LR * s;
        }
        for (int c = gw; c < H4; c += nb * 16) {
            float s = 0.f;
            for (int n = lane; n < NB; n += 32) s += g_da[(size_t)n * H4 + c];
#pragma unroll
            for (int o = 16; o > 0; o >>= 1) s += __shfl_xor_sync(0xffffffffu, s, o);
            if (lane == 0) g_b1[c] -= LR * s;
        }
        grid_sync(nb);

        // ---- R6: a2 partials = Qt @ W1_new^T (128 units) ----
        for (int u = ubase; u < 128; u += ustride) {
            int sk = u & 7, tile = u >> 3;
            int m0 = (tile & 3) * 64, n0 = (tile >> 2) * 64;
            float acc[4][4] = {};
            tile_db<0>(Qt, g_W1, hsm, DD, DD, m0, n0, sk * 128, sk * 128 + 128,
                       htid, acc);
            float* cp = g_part + (size_t)sk * MN;
#pragma unroll
            for (int r = 0; r < 4; r++)
                *(float4*)(cp + (size_t)(m0 + ty * 4 + r) * H4 + n0 + tx * 4) =
                    make_float4(acc[r][0], acc[r][1], acc[r][2], acc[r][3]);
        }
        grid_sync(nb);

        // ---- R7: h2 = gelu(sum(part) + b1_new) ----
        for (int idx = bid * 512 + tid; idx < MN; idx += nb * 512) {
            float s = 0.f;
#pragma unroll
            for (int z = 0; z < 8; z++) s += g_part[(size_t)z * MN + idx];
            s += g_b1[idx & (H4 - 1)];
            g_h2[idx] = gelu_f(s);
        }
        grid_sync(nb);
    }
}

// ---------------------------------------------------------------------------
// kernel_launch
// ---------------------------------------------------------------------------
extern "C" void kernel_launch(void* const* d_in, const int* in_sizes, int n_in,
                              void* d_out, int out_size)
{
    (void)in_sizes; (void)n_in; (void)out_size;
    const float* in_seq = (const float*)d_in[0];
    const float* t_k = (const float*)d_in[1];
    const float* t_v = (const float*)d_in[2];
    const float* t_q = (const float*)d_in[3];

    float *Z, *Y, *Q, *W1, *b1, *W2, *b2;
    cudaGetSymbolAddress((void**)&Z, g_Z);
    cudaGetSymbolAddress((void**)&Y, g_Y);
    cudaGetSymbolAddress((void**)&Q, g_Q);
    cudaGetSymbolAddress((void**)&W1, g_W1);
    cudaGetSymbolAddress((void**)&b1, g_b1);
    cudaGetSymbolAddress((void**)&W2, g_W2);
    cudaGetSymbolAddress((void**)&b2, g_b2);

    cudaMemcpyAsync(W1, d_in[4], sizeof(float) * H4 * HH, cudaMemcpyDeviceToDevice, 0);
    cudaMemcpyAsync(b1, d_in[5], sizeof(float) * H4, cudaMemcpyDeviceToDevice, 0);
    cudaMemcpyAsync(W2, d_in[6], sizeof(float) * HH * H4, cudaMemcpyDeviceToDevice, 0);
    cudaMemcpyAsync(b2, d_in[7], sizeof(float) * HH, cudaMemcpyDeviceToDevice, 0);

    // Phase A: tf32 tensor-core GEMMs
    const int M_big = T_ * NB;
    dim3 gA(M_big / 128, HH / 128);
    gemm_nt_tf32<<<gA, 256>>>(in_seq, t_k, Z, M_big, HH, DD);
    gemm_nt_tf32<<<gA, 256>>>(in_seq, t_v, Y, M_big, HH, DD);
    gemm_nt_tf32<<<gA, 256>>>(in_seq, t_q, Q, M_big, HH, DD);

    // Phase B: one persistent kernel, exactly one block per SM.
    int sms = 0;
    cudaDeviceGetAttribute(&sms, cudaDevAttrMultiProcessorCount, 0);
    if (sms <= 0 || sms > 148) sms = 148;
    ttt_persistent<<<sms, 512>>>((float*)d_out, sms);
}